// round 16
// baseline (speedup 1.0000x reference)
#include <cuda_runtime.h>
#include <math.h>
#include <stdint.h>

#define NRES 1024
#define CS   384
#define CATD 2112

typedef unsigned long long ull;

__device__ __forceinline__ void ffma2(ull &d, ull a, ull b) {
    asm("fma.rn.f32x2 %0, %1, %2, %0;" : "+l"(d) : "l"(a), "l"(b));
}
__device__ __forceinline__ float2 unpack2(ull v) {
    float2 r; asm("mov.b64 {%0, %1}, %2;" : "=f"(r.x), "=f"(r.y) : "l"(v)); return r;
}
__device__ __forceinline__ void cp16(uint32_t dst, const void* src) {
    asm volatile("cp.async.cg.shared.global [%0], [%1], 16;" :: "r"(dst), "l"(src));
}
__device__ __forceinline__ void cp_commit() { asm volatile("cp.async.commit_group;"); }
__device__ __forceinline__ void cp_wait1() { asm volatile("cp.async.wait_group 1;"); }
__device__ __forceinline__ void cp_wait0() { asm volatile("cp.async.wait_group 0;"); }

// ---------------- scratch ----------------
static const size_t SZ_Q    = (size_t)NRES*192;
static const size_t SZ_KV   = (size_t)NRES*384;
static const size_t SZ_QPR  = (size_t)NRES*144;
static const size_t SZ_KVPR = (size_t)NRES*432;
static const size_t SZ_KVP  = (size_t)NRES*432;
static const size_t SZ_QT   = (size_t)NRES*384;
static const size_t SZ_KT   = (size_t)NRES*384;
static const size_t SZ_A    = (size_t)12*NRES*NRES;
static const size_t SZ_OP   = (size_t)NRES*288;
static const size_t SZ_CAT  = (size_t)NRES*CATD;
static const size_t SZ_S    = (size_t)NRES*CS;
static const size_t SZ_UPD  = (size_t)NRES*8;

static const size_t OFF_Q    = 0;
static const size_t OFF_KV   = OFF_Q    + SZ_Q;
static const size_t OFF_QPR  = OFF_KV   + SZ_KV;
static const size_t OFF_KVPR = OFF_QPR  + SZ_QPR;
static const size_t OFF_KVP  = OFF_KVPR + SZ_KVPR;
static const size_t OFF_QT   = OFF_KVP  + SZ_KVP;
static const size_t OFF_KT   = OFF_QT   + SZ_QT;
static const size_t OFF_A    = OFF_KT   + SZ_KT;
static const size_t OFF_OP   = OFF_A    + SZ_A;
static const size_t OFF_CAT  = OFF_OP   + SZ_OP;
static const size_t OFF_SA   = OFF_CAT  + SZ_CAT;
static const size_t OFF_S1   = OFF_SA   + SZ_S;
static const size_t OFF_H1   = OFF_S1   + SZ_S;
static const size_t OFF_H2   = OFF_H1   + SZ_S;
static const size_t OFF_SB   = OFF_H2   + SZ_S;
static const size_t OFF_UPD  = OFF_SB   + SZ_S;

__device__ __align__(16) float g_scratch[OFF_UPD + SZ_UPD];

// ---------------- generic GEMM (32x64 tiles, 128 thr): C = A@W^T + bias (+res) ----------------
__global__ void gemm_kernel(const float* __restrict__ A, const float* __restrict__ W,
                            const float* __restrict__ bias, const float* __restrict__ res,
                            float* __restrict__ C, int M, int N, int K, int relu)
{
    __shared__ float As[16][36];
    __shared__ float Ws[16][68];
    const int t = threadIdx.x;          // 128
    const int bm = blockIdx.y * 32, bn = blockIdx.x * 64;
    const int tx = t & 15, ty = t >> 4; // ty 0..7

    float acc[4][4];
#pragma unroll
    for (int r = 0; r < 4; r++)
#pragma unroll
        for (int c = 0; c < 4; c++) acc[r][c] = 0.f;

    const int rowA = t >> 2, kqA = t & 3;
    for (int k0 = 0; k0 < K; k0 += 16) {
        float4 a4 = *(const float4*)(A + (size_t)(bm + rowA) * K + k0 + kqA * 4);
        As[kqA*4+0][rowA] = a4.x; As[kqA*4+1][rowA] = a4.y;
        As[kqA*4+2][rowA] = a4.z; As[kqA*4+3][rowA] = a4.w;
#pragma unroll
        for (int u0 = 0; u0 < 2; u0++) {
            int u = t + u0 * 128;
            int row = u >> 2, kq = u & 3;
            int gn = bn + row;
            float4 w4 = make_float4(0.f, 0.f, 0.f, 0.f);
            if (gn < N) w4 = *(const float4*)(W + (size_t)gn * K + k0 + kq * 4);
            Ws[kq*4+0][row] = w4.x; Ws[kq*4+1][row] = w4.y;
            Ws[kq*4+2][row] = w4.z; Ws[kq*4+3][row] = w4.w;
        }
        __syncthreads();
#pragma unroll
        for (int kk = 0; kk < 16; kk++) {
            float4 av = *(const float4*)&As[kk][ty * 4];
            float4 bv = *(const float4*)&Ws[kk][tx * 4];
            float ar[4] = {av.x, av.y, av.z, av.w};
            float br[4] = {bv.x, bv.y, bv.z, bv.w};
#pragma unroll
            for (int r = 0; r < 4; r++)
#pragma unroll
                for (int c = 0; c < 4; c++) acc[r][c] += ar[r] * br[c];
        }
        __syncthreads();
    }
#pragma unroll
    for (int r = 0; r < 4; r++) {
        int gm = bm + ty * 4 + r;
#pragma unroll
        for (int c = 0; c < 4; c++) {
            int gn = bn + tx * 4 + c;
            if (gn < N) {
                float v = acc[r][c] + bias[gn];
                if (res) v += res[(size_t)gm * N + gn];
                if (relu) v = fmaxf(v, 0.f);
                C[(size_t)gm * N + gn] = v;
            }
        }
    }
}

// ---------------- split-K GEMM (z halves K, atomicAdd into zeroed C) ----------------
__global__ void gemm_splitk_kernel(const float* __restrict__ A, const float* __restrict__ W,
                                   const float* __restrict__ bias, const float* __restrict__ res,
                                   float* __restrict__ C, int M, int N, int K, int relu_in)
{
    __shared__ float As[16][36];
    __shared__ float Ws[16][68];
    const int t = threadIdx.x;          // 128
    const int bm = blockIdx.y * 32, bn = blockIdx.x * 64;
    const int tx = t & 15, ty = t >> 4;
    const int kz = blockIdx.z;          // 0 or 1
    const int kbeg = kz * (K / 2), kend = kbeg + K / 2;

    float acc[4][4];
#pragma unroll
    for (int r = 0; r < 4; r++)
#pragma unroll
        for (int c = 0; c < 4; c++) acc[r][c] = 0.f;

    const int rowA = t >> 2, kqA = t & 3;
    for (int k0 = kbeg; k0 < kend; k0 += 16) {
        float4 a4 = *(const float4*)(A + (size_t)(bm + rowA) * K + k0 + kqA * 4);
        if (relu_in) {
            a4.x = fmaxf(a4.x, 0.f); a4.y = fmaxf(a4.y, 0.f);
            a4.z = fmaxf(a4.z, 0.f); a4.w = fmaxf(a4.w, 0.f);
        }
        As[kqA*4+0][rowA] = a4.x; As[kqA*4+1][rowA] = a4.y;
        As[kqA*4+2][rowA] = a4.z; As[kqA*4+3][rowA] = a4.w;
#pragma unroll
        for (int u0 = 0; u0 < 2; u0++) {
            int u = t + u0 * 128;
            int row = u >> 2, kq = u & 3;
            int gn = bn + row;
            float4 w4 = make_float4(0.f, 0.f, 0.f, 0.f);
            if (gn < N) w4 = *(const float4*)(W + (size_t)gn * K + k0 + kq * 4);
            Ws[kq*4+0][row] = w4.x; Ws[kq*4+1][row] = w4.y;
            Ws[kq*4+2][row] = w4.z; Ws[kq*4+3][row] = w4.w;
        }
        __syncthreads();
#pragma unroll
        for (int kk = 0; kk < 16; kk++) {
            float4 av = *(const float4*)&As[kk][ty * 4];
            float4 bv = *(const float4*)&Ws[kk][tx * 4];
            float ar[4] = {av.x, av.y, av.z, av.w};
            float br[4] = {bv.x, bv.y, bv.z, bv.w};
#pragma unroll
            for (int r = 0; r < 4; r++)
#pragma unroll
                for (int c = 0; c < 4; c++) acc[r][c] += ar[r] * br[c];
        }
        __syncthreads();
    }
#pragma unroll
    for (int r = 0; r < 4; r++) {
        int gm = bm + ty * 4 + r;
#pragma unroll
        for (int c = 0; c < 4; c++) {
            int gn = bn + tx * 4 + c;
            if (gn < N) {
                float v = acc[r][c];
                if (kz == 0) {
                    v += bias[gn];
                    if (res) v += res[(size_t)gm * N + gn];
                }
                atomicAdd(&C[(size_t)gm * N + gn], v);
            }
        }
    }
}

// ---------------- combined projection GEMM (4 weight matrices, 48-col tiles) ----------------
__global__ void proj_kernel(const float* __restrict__ S,
                            const float* __restrict__ wq,   const float* __restrict__ bq,
                            const float* __restrict__ wkv,  const float* __restrict__ bkv,
                            const float* __restrict__ wqp,  const float* __restrict__ bqp,
                            const float* __restrict__ wkvp, const float* __restrict__ bkvp,
                            float* __restrict__ q, float* __restrict__ kvb,
                            float* __restrict__ qpr, float* __restrict__ kvpr)
{
    __shared__ float As[16][68];
    __shared__ float Ws[16][52];
    const int bx = blockIdx.x, bm = blockIdx.y * 64;
    const float *W, *B; float* O; int nbase, N;
    if (bx < 4)       { W = wq;   B = bq;   O = q;    nbase = bx * 48;        N = 192; }
    else if (bx < 12) { W = wkv;  B = bkv;  O = kvb;  nbase = (bx - 4) * 48;  N = 384; }
    else if (bx < 15) { W = wqp;  B = bqp;  O = qpr;  nbase = (bx - 12) * 48; N = 144; }
    else              { W = wkvp; B = bkvp; O = kvpr; nbase = (bx - 15) * 48; N = 432; }

    const int t = threadIdx.x;           // 256
    const int tx = t & 15, ty = t >> 4;
    const int row = t >> 2, kq = t & 3;

    float acc[4][3];
#pragma unroll
    for (int r = 0; r < 4; r++)
#pragma unroll
        for (int c = 0; c < 3; c++) acc[r][c] = 0.f;

    for (int k0 = 0; k0 < 384; k0 += 16) {
        float4 a4 = *(const float4*)(S + (size_t)(bm + row) * 384 + k0 + kq * 4);
        As[kq*4+0][row] = a4.x; As[kq*4+1][row] = a4.y;
        As[kq*4+2][row] = a4.z; As[kq*4+3][row] = a4.w;
        if (t < 192) {
            float4 w4 = *(const float4*)(W + (size_t)(nbase + row) * 384 + k0 + kq * 4);
            Ws[kq*4+0][row] = w4.x; Ws[kq*4+1][row] = w4.y;
            Ws[kq*4+2][row] = w4.z; Ws[kq*4+3][row] = w4.w;
        }
        __syncthreads();
#pragma unroll
        for (int kk = 0; kk < 16; kk++) {
            float4 av = *(const float4*)&As[kk][ty * 4];
            float ar[4] = {av.x, av.y, av.z, av.w};
            float w0 = Ws[kk][tx*3 + 0], w1 = Ws[kk][tx*3 + 1], w2 = Ws[kk][tx*3 + 2];
#pragma unroll
            for (int r = 0; r < 4; r++) {
                acc[r][0] += ar[r] * w0; acc[r][1] += ar[r] * w1; acc[r][2] += ar[r] * w2;
            }
        }
        __syncthreads();
    }
#pragma unroll
    for (int r = 0; r < 4; r++) {
        int gm = bm + ty * 4 + r;
#pragma unroll
        for (int c = 0; c < 3; c++) {
            int n = nbase + tx * 3 + c;
            O[(size_t)gm * N + n] = acc[r][c] + B[n];
        }
    }
}

// ---------------- rotate points + pack q~/k~ (kt transposed to [h][c][j]) ----------------
__global__ void rotpack_kernel(const float* __restrict__ qpr, const float* __restrict__ kvpr,
                               const float* __restrict__ rots, const float* __restrict__ trans,
                               const float* __restrict__ q, const float* __restrict__ kv,
                               const float* __restrict__ head_w,
                               float* __restrict__ qt, float* __restrict__ kt_t,
                               float* __restrict__ kvp_out)
{
    __shared__ float R[9], tr[3];
    __shared__ float qp_s[144], kvp_s[432], q2_s[48], k2_s[48];
    const int i = blockIdx.x, t = threadIdx.x; // 384 threads
    if (t < 9) R[t] = rots[i * 9 + t];
    if (t < 3) tr[t] = trans[i * 3 + t];
    __syncthreads();
    if (t < 48) {
        float r0 = qpr[(size_t)i * 144 + 0 * 48 + t];
        float r1 = qpr[(size_t)i * 144 + 1 * 48 + t];
        float r2 = qpr[(size_t)i * 144 + 2 * 48 + t];
        float v0 = R[0]*r0 + R[1]*r1 + R[2]*r2 + tr[0];
        float v1 = R[3]*r0 + R[4]*r1 + R[5]*r2 + tr[1];
        float v2 = R[6]*r0 + R[7]*r1 + R[8]*r2 + tr[2];
        qp_s[t * 3 + 0] = v0; qp_s[t * 3 + 1] = v1; qp_s[t * 3 + 2] = v2;
        q2_s[t] = v0*v0 + v1*v1 + v2*v2;
    } else if (t < 192) {
        int u = t - 48; // < 144
        float r0 = kvpr[(size_t)i * 432 + 0 * 144 + u];
        float r1 = kvpr[(size_t)i * 432 + 1 * 144 + u];
        float r2 = kvpr[(size_t)i * 432 + 2 * 144 + u];
        float v0 = R[0]*r0 + R[1]*r1 + R[2]*r2 + tr[0];
        float v1 = R[3]*r0 + R[4]*r1 + R[5]*r2 + tr[1];
        float v2 = R[6]*r0 + R[7]*r1 + R[8]*r2 + tr[2];
        kvp_s[u * 3 + 0] = v0; kvp_s[u * 3 + 1] = v1; kvp_s[u * 3 + 2] = v2;
        kvp_out[(size_t)i * 432 + u * 3 + 0] = v0;
        kvp_out[(size_t)i * 432 + u * 3 + 1] = v1;
        kvp_out[(size_t)i * 432 + u * 3 + 2] = v2;
        int idx = u % 12, h = u / 12;
        if (idx < 4) k2_s[h * 4 + idx] = v0*v0 + v1*v1 + v2*v2;
    }
    __syncthreads();

    const int h = t >> 5, c = t & 31;
    const float hw = -0.5f * log1pf(expf(head_w[h])) * 0.13608276f;
    float qv = 0.f, kvv = 0.f;
    if (c < 16) {
        qv  = q [(size_t)i * 192 + h * 16 + c] * 0.14433757f;
        kvv = kv[(size_t)i * 384 + h * 32 + c];
    } else if (c < 28) {
        qv  = qp_s[h * 12 + (c - 16)];
        kvv = -2.f * hw * kvp_s[h * 36 + (c - 16)];
    } else if (c == 28) {
        const float* s = q2_s + h * 4;
        qv  = hw * (s[0] + s[1] + s[2] + s[3]);
        kvv = 1.f;
    } else if (c == 29) {
        const float* s = k2_s + h * 4;
        qv  = 1.f;
        kvv = hw * (s[0] + s[1] + s[2] + s[3]);
    }
    qt[((size_t)i * 12 + h) * 32 + c] = qv;
    kt_t[(((size_t)h * 32 + c) << 10) + i] = kvv;   // [h][c][j] transposed
}

// ---------------- bias over p (p-pass 1): cp.async double-buffered ----------------
__global__ void __launch_bounds__(256, 2)
bias_kernel(const float* __restrict__ p, const float* __restrict__ wb,
            const float* __restrict__ bbias, const float* __restrict__ mask,
            float* __restrict__ A)
{
    extern __shared__ float sh[];
    float* wb_s = sh;                              // [12][128] = 1536
    const int t = threadIdx.x, w = t >> 5, lane = t & 31;
    float* p_w = sh + 1536 + w * (2 * 64 * 20);

    for (int u = t; u < 384; u += 256)
        ((float4*)wb_s)[u] = ((const float4*)wb)[u];
    __syncthreads();

    const size_t pair0 = (size_t)blockIdx.x * 512 + (size_t)w * 64;
    const float* psrc = p + pair0 * 128;
    uint32_t pb0 = (uint32_t)__cvta_generic_to_shared(p_w);
    const uint32_t pbuf[2] = {pb0, pb0 + 64 * 20 * 4};

#pragma unroll
    for (int v = 0; v < 8; v++) {
        int u = lane + v * 32;
        int row = u >> 2, c4 = u & 3;
        cp16(pbuf[0] + (uint32_t)(row * 20 + c4 * 4) * 4,
             psrc + (size_t)row * 128 + c4 * 4);
    }
    cp_commit();

    ull acc[2][12];
#pragma unroll
    for (int pp = 0; pp < 2; pp++)
#pragma unroll
        for (int h = 0; h < 12; h++) acc[pp][h] = 0ull;

#pragma unroll
    for (int ch = 0; ch < 8; ch++) {
        if (ch < 7) {
            const float* src = psrc + (ch + 1) * 16;
            uint32_t db = pbuf[(ch + 1) & 1];
#pragma unroll
            for (int v = 0; v < 8; v++) {
                int u = lane + v * 32;
                int row = u >> 2, c4 = u & 3;
                cp16(db + (uint32_t)(row * 20 + c4 * 4) * 4,
                     src + (size_t)row * 128 + c4 * 4);
            }
            cp_commit();
            cp_wait1();
        } else {
            cp_wait0();
        }
        __syncwarp();
        const float* pw = p_w + (ch & 1) * (64 * 20);
        const ulonglong2* prow0 = (const ulonglong2*)(pw + (size_t)lane * 20);
        const ulonglong2* prow1 = (const ulonglong2*)(pw + (size_t)(lane + 32) * 20);
        const float* wbq = wb_s + ch * 16;
#pragma unroll
        for (int z4 = 0; z4 < 4; z4++) {
            ulonglong2 a0 = prow0[z4], a1 = prow1[z4];
#pragma unroll
            for (int h = 0; h < 12; h++) {
                ulonglong2 wv = *(const ulonglong2*)(wbq + h * 128 + z4 * 4);
                ffma2(acc[0][h], wv.x, a0.x); ffma2(acc[0][h], wv.y, a0.y);
                ffma2(acc[1][h], wv.x, a1.x); ffma2(acc[1][h], wv.y, a1.y);
            }
        }
        __syncwarp();
    }

#pragma unroll
    for (int pp = 0; pp < 2; pp++) {
        const size_t pair = pair0 + lane + pp * 32;
        const int i = (int)(pair >> 10), j = (int)(pair & 1023);
        const float mterm = 100000.0f * (mask[i] * mask[j] - 1.0f);
#pragma unroll
        for (int h = 0; h < 12; h++) {
            float2 r = unpack2(acc[pp][h]);
            A[((size_t)h << 20) + pair] = 0.57735027f * (r.x + r.y + bbias[h]) + mterm;
        }
    }
}

// ---------------- fused qk/point logits + row softmax (kt staged ONCE in smem) ----------------
// grid (32 i-tiles of 32 rows, 12 h), 256 threads. Thread owns j = 4t..4t+3.
__global__ void __launch_bounds__(256, 1)
attn_kernel(const float* __restrict__ qt, const float* __restrict__ kt_t,
            float* __restrict__ A)
{
    extern __shared__ float ash[];
    float* kt_s    = ash;                 // [32][1024]
    float* qd_s    = ash + 32 * 1024;     // [32][64] q duplicated
    float* red     = qd_s + 2048;         // [32]
    float* rowstat = red + 32;            // [8]
    const int t = threadIdx.x;
    const int lane = t & 31, w = t >> 5;
    const int h = blockIdx.y;
    const int i0 = blockIdx.x * 32;
    float* Ah = A + ((size_t)h << 20);
    const float* kth = kt_t + ((size_t)h << 15);   // [32][1024]

    // stage kt once (32768 floats = 8192 float4)
    for (int u = t; u < 8192; u += 256) {
        int c = u >> 8, j4 = u & 255;
        *(float4*)&kt_s[c * 1024 + j4 * 4] = *(const float4*)&kth[(size_t)c * 1024 + j4 * 4];
    }
    for (int u = t; u < 1024; u += 256) {
        int il = u >> 5, c = u & 31;
        float v = qt[((size_t)(i0 + il) * 12 + h) * 32 + c];
        qd_s[il * 64 + c * 2]     = v;
        qd_s[il * 64 + c * 2 + 1] = v;
    }
    __syncthreads();

    for (int g = 0; g < 8; g++) {
        const int ibase = i0 + g * 4;

        float4 lg4[4];
#pragma unroll
        for (int r = 0; r < 4; r++)
            lg4[r] = *(const float4*)&Ah[(size_t)(ibase + r) * 1024 + 4 * t];

        ull acc[4][2];
#pragma unroll
        for (int r = 0; r < 4; r++) { acc[r][0] = 0ull; acc[r][1] = 0ull; }

#pragma unroll 4
        for (int c2 = 0; c2 < 16; c2++) {
            ulonglong2 k0u = *(const ulonglong2*)&kt_s[(2 * c2) * 1024 + 4 * t];
            ulonglong2 k1u = *(const ulonglong2*)&kt_s[(2 * c2 + 1) * 1024 + 4 * t];
#pragma unroll
            for (int r = 0; r < 4; r++) {
                ulonglong2 q2 = *(const ulonglong2*)&qd_s[(g * 4 + r) * 64 + c2 * 4];
                ffma2(acc[r][0], q2.x, k0u.x); ffma2(acc[r][1], q2.x, k0u.y);
                ffma2(acc[r][0], q2.y, k1u.x); ffma2(acc[r][1], q2.y, k1u.y);
            }
        }
#pragma unroll
        for (int r = 0; r < 4; r++) {
            float2 lo = unpack2(acc[r][0]);
            float2 hi = unpack2(acc[r][1]);
            lg4[r].x += lo.x; lg4[r].y += lo.y;
            lg4[r].z += hi.x; lg4[r].w += hi.y;
        }

        float m4[4];
#pragma unroll
        for (int r = 0; r < 4; r++)
            m4[r] = fmaxf(fmaxf(lg4[r].x, lg4[r].y), fmaxf(lg4[r].z, lg4[r].w));
#pragma unroll
        for (int off = 16; off >= 1; off >>= 1)
#pragma unroll
            for (int r = 0; r < 4; r++)
                m4[r] = fmaxf(m4[r], __shfl_xor_sync(0xffffffffu, m4[r], off));
        if (lane == 0)
#pragma unroll
            for (int r = 0; r < 4; r++) red[r * 8 + w] = m4[r];
        __syncthreads();
        if (t < 4) {
            float v = red[t * 8];
#pragma unroll
            for (int ww = 1; ww < 8; ww++) v = fmaxf(v, red[t * 8 + ww]);
            rowstat[t] = v;
        }
        __syncthreads();

        float s4[4];
#pragma unroll
        for (int r = 0; r < 4; r++) {
            const float M = rowstat[r];
            lg4[r].x = __expf(lg4[r].x - M);
            lg4[r].y = __expf(lg4[r].y - M);
            lg4[r].z = __expf(lg4[r].z - M);
            lg4[r].w = __expf(lg4[r].w - M);
            s4[r] = lg4[r].x + lg4[r].y + lg4[r].z + lg4[r].w;
        }
#pragma unroll
        for (int off = 16; off >= 1; off >>= 1)
#pragma unroll
            for (int r = 0; r < 4; r++)
                s4[r] += __shfl_xor_sync(0xffffffffu, s4[r], off);
        if (lane == 0)
#pragma unroll
            for (int r = 0; r < 4; r++) red[r * 8 + w] = s4[r];
        __syncthreads();
        if (t < 4) {
            float v = red[t * 8];
#pragma unroll
            for (int ww = 1; ww < 8; ww++) v += red[t * 8 + ww];
            rowstat[4 + t] = 1.f / v;
        }
        __syncthreads();

#pragma unroll
        for (int r = 0; r < 4; r++) {
            const float inv = rowstat[4 + r];
            float4 o = make_float4(lg4[r].x * inv, lg4[r].y * inv,
                                   lg4[r].z * inv, lg4[r].w * inv);
            *(float4*)&Ah[(size_t)(ibase + r) * 1024 + 4 * t] = o;
        }
        __syncthreads();
    }
}

// ---------------- O = A_h @ [v | vp]  (32-row tiles) ----------------
__global__ void av_kernel(const float* __restrict__ A, const float* __restrict__ kv,
                          const float* __restrict__ kvp,
                          float* __restrict__ cat, float* __restrict__ opb)
{
    __shared__ float A_s[32][33];
    __shared__ float B_s[32][40];
    const int h = blockIdx.y, i0 = blockIdx.x * 32;
    const int tid = threadIdx.x;         // 128
    const int m = tid & 31, sct = tid >> 5;
    const float* Ah = A + ((size_t)h << 20);
    float acc[10];
#pragma unroll
    for (int n = 0; n < 10; n++) acc[n] = 0.f;

    for (int k0 = 0; k0 < 1024; k0 += 32) {
        for (int u = tid; u < 1024; u += 128) {
            int mm = u >> 5, kk = u & 31;
            A_s[kk][mm] = Ah[(size_t)(i0 + mm) * 1024 + k0 + kk];
        }
        for (int u = tid; u < 1280; u += 128) {
            int kk = u / 40, n = u % 40;
            int jgl = k0 + kk;
            B_s[kk][n] = (n < 16) ? kv [(size_t)jgl * 384 + h * 32 + 16 + n]
                                  : kvp[(size_t)jgl * 432 + h * 36 + 12 + (n - 16)];
        }
        __syncthreads();
#pragma unroll
        for (int kk = 0; kk < 32; kk++) {
            float a = A_s[kk][m];
#pragma unroll
            for (int n2 = 0; n2 < 5; n2++) {
                float2 b = *(const float2*)&B_s[kk][sct * 10 + n2 * 2];
                acc[n2*2+0] += a * b.x; acc[n2*2+1] += a * b.y;
            }
        }
        __syncthreads();
    }
    const int i = i0 + m;
#pragma unroll
    for (int n = 0; n < 10; n++) {
        int gn = sct * 10 + n;
        if (gn < 16) cat[(size_t)i * CATD + h * 16 + gn] = acc[n];
        else         opb[(size_t)i * 288 + h * 24 + (gn - 16)] = acc[n];
    }
}

// ---------------- opair (p-pass 2): cp.async double-buffered ----------------
__global__ void __launch_bounds__(128, 2)
opair_kernel(const float* __restrict__ p, const float* __restrict__ A,
             float* __restrict__ cat)
{
    extern __shared__ float sh[];
    const int t = threadIdx.x;
    const int w = t >> 5, lane = t & 31;
    const int iw = w >> 1, zh = w & 1;
    const int i = blockIdx.x * 2 + iw;
    float* p_w = sh + w * (2 * 32 * 68);
    ull*   a_w = (ull*)(sh + 4 * 2 * 32 * 68) + w * (2 * 12 * 32);

    const float* psrc = p + (size_t)i * 1024 * 128 + zh * 64;
    uint32_t pb0 = (uint32_t)__cvta_generic_to_shared(p_w);
    const uint32_t pbuf[2] = {pb0, pb0 + 32 * 68 * 4};

#pragma unroll
    for (int v = 0; v < 16; v++) {
        int u = lane + v * 32;
        int row = u >> 4, c4 = u & 15;
        cp16(pbuf[0] + (uint32_t)(row * 68 + c4 * 4) * 4,
             psrc + (size_t)row * 128 + c4 * 4);
    }
    cp_commit();
#pragma unroll
    for (int v = 0; v < 12; v++) {
        int u = lane + v * 32;
        int h = u >> 5, jj = u & 31;
        float a = A[((size_t)h << 20) + (size_t)i * 1024 + jj];
        float2 a2 = make_float2(a, a);
        a_w[h * 32 + jj] = *(ull*)&a2;
    }

    ull acc[12];
#pragma unroll
    for (int h = 0; h < 12; h++) acc[h] = 0ull;

    for (int c = 0; c < 32; c++) {
        if (c < 31) {
            const int j1 = (c + 1) * 32;
            uint32_t db = pbuf[(c + 1) & 1];
            const float* src = psrc + (size_t)j1 * 128;
#pragma unroll
            for (int v = 0; v < 16; v++) {
                int u = lane + v * 32;
                int row = u >> 4, c4 = u & 15;
                cp16(db + (uint32_t)(row * 68 + c4 * 4) * 4,
                     src + (size_t)row * 128 + c4 * 4);
            }
            cp_commit();
            ull* ab = a_w + ((c + 1) & 1) * (12 * 32);
#pragma unroll
            for (int v = 0; v < 12; v++) {
                int u = lane + v * 32;
                int h = u >> 5, jj = u & 31;
                float a = A[((size_t)h << 20) + (size_t)i * 1024 + j1 + jj];
                float2 a2 = make_float2(a, a);
                ab[h * 32 + jj] = *(ull*)&a2;
            }
            cp_wait1();
        } else {
            cp_wait0();
        }
        __syncwarp();
        const float* pw = p_w + (c & 1) * (32 * 68);
        const ull* aw = a_w + (c & 1) * (12 * 32);
#pragma unroll 8
        for (int jj = 0; jj < 32; jj++) {
            ull pv = *(const ull*)&pw[jj * 68 + lane * 2];
            const ull* arow = aw + jj;
#pragma unroll
            for (int h = 0; h < 12; h++)
                ffma2(acc[h], arow[h * 32], pv);
        }
        __syncwarp();
    }
#pragma unroll
    for (int h = 0; h < 12; h++) {
        float2 r = unpack2(acc[h]);
        *(float2*)&cat[(size_t)i * CATD + 576 + h * 128 + zh * 64 + lane * 2] = r;
    }
}

// ---------------- transform op back to local frame + norms ----------------
__global__ void op_transform_kernel(const float* __restrict__ opb, const float* __restrict__ rots,
                                    const float* __restrict__ trans, float* __restrict__ cat)
{
    const int i = blockIdx.x, t = threadIdx.x; // 96 points
    __shared__ float R[9], tr[3];
    if (t < 9) R[t] = rots[i * 9 + t];
    if (t < 3) tr[t] = trans[i * 3 + t];
    __syncthreads();
    float v0 = opb[(size_t)i * 288 + t * 3 + 0] - tr[0];
    float v1 = opb[(size_t)i * 288 + t * 3 + 1] - tr[1];
    float v2 = opb[(size_t)i * 288 + t * 3 + 2] - tr[2];
    float l0 = R[0]*v0 + R[3]*v1 + R[6]*v2;
    float l1 = R[1]*v0 + R[4]*v1 + R[7]*v2;
    float l2 = R[2]*v0 + R[5]*v1 + R[8]*v2;
    float* c = cat + (size_t)i * CATD;
    c[192 + t] = l0;
    c[288 + t] = l1;
    c[384 + t] = l2;
    c[480 + t] = sqrtf(l0*l0 + l1*l1 + l2*l2 + 1e-8f);
}

// ---------------- LayerNorm (row = 384) ----------------
__global__ void ln_kernel(const float* __restrict__ x, const float* __restrict__ g,
                          const float* __restrict__ b, float* __restrict__ out)
{
    __shared__ float s1[384], s2[384];
    const int row = blockIdx.x, t = threadIdx.x;
    float v = x[(size_t)row * 384 + t];
    s1[t] = v; s2[t] = v * v;
    __syncthreads();
    if (t < 128) { s1[t] += s1[t + 256]; s2[t] += s2[t + 256]; }
    __syncthreads();
    for (int s = 128; s > 0; s >>= 1) {
        if (t < s) { s1[t] += s1[t + s]; s2[t] += s2[t + s]; }
        __syncthreads();
    }
    float mean = s1[0] * (1.f / 384.f);
    float var  = s2[0] * (1.f / 384.f) - mean * mean;
    float inv  = rsqrtf(var + 1e-5f);
    out[(size_t)row * 384 + t] = (v - mean) * inv * g[t] + b[t];
}

// ---------------- final quaternion / frame update ----------------
__global__ void final_pose_kernel(const float* __restrict__ upd, const float* __restrict__ rots,
                                  const float* __restrict__ trans, float* __restrict__ out)
{
    const int i = blockIdx.x * blockDim.x + threadIdx.x;
    if (i >= NRES) return;
    const float* u = upd + (size_t)i * 6;
    float x = u[0], y = u[1], z = u[2];
    float inv = rsqrtf(1.f + x*x + y*y + z*z);
    float w = inv; x *= inv; y *= inv; z *= inv;
    float U[9];
    U[0] = w*w + x*x - y*y - z*z; U[1] = 2.f*(x*y - w*z);       U[2] = 2.f*(x*z + w*y);
    U[3] = 2.f*(x*y + w*z);       U[4] = w*w - x*x + y*y - z*z; U[5] = 2.f*(y*z - w*x);
    U[6] = 2.f*(x*z - w*y);       U[7] = 2.f*(y*z + w*x);       U[8] = w*w - x*x - y*y + z*z;
    const float* R = rots + (size_t)i * 9;
    float* Ro = out + 393216 + (size_t)i * 9;
#pragma unroll
    for (int r = 0; r < 3; r++)
#pragma unroll
        for (int c = 0; c < 3; c++)
            Ro[r*3+c] = R[r*3+0]*U[0*3+c] + R[r*3+1]*U[1*3+c] + R[r*3+2]*U[2*3+c];
    float* To = out + 402432 + (size_t)i * 3;
#pragma unroll
    for (int r = 0; r < 3; r++)
        To[r] = R[r*3+0]*u[3] + R[r*3+1]*u[4] + R[r*3+2]*u[5] + trans[(size_t)i*3 + r];
}

// ---------------- launch ----------------
extern "C" void kernel_launch(void* const* d_in, const int* in_sizes, int n_in,
                              void* d_out, int out_size)
{
    const float* s_in  = (const float*)d_in[0];
    const float* p     = (const float*)d_in[1];
    const float* rots  = (const float*)d_in[2];
    const float* trans = (const float*)d_in[3];
    const float* mask  = (const float*)d_in[4];
    const float* wq    = (const float*)d_in[5];
    const float* bq    = (const float*)d_in[6];
    const float* wkv   = (const float*)d_in[7];
    const float* bkv   = (const float*)d_in[8];
    const float* wqp   = (const float*)d_in[9];
    const float* bqp   = (const float*)d_in[10];
    const float* wkvp  = (const float*)d_in[11];
    const float* bkvp  = (const float*)d_in[12];
    const float* wb    = (const float*)d_in[13];
    const float* bbias = (const float*)d_in[14];
    const float* head_w= (const float*)d_in[15];
    const float* wo    = (const float*)d_in[16];
    const float* bo    = (const float*)d_in[17];
    const float* ln1_g = (const float*)d_in[18];
    const float* ln1_b = (const float*)d_in[19];
    const float* tw1   = (const float*)d_in[20];
    const float* tb1   = (const float*)d_in[21];
    const float* tw2   = (const float*)d_in[22];
    const float* tb2   = (const float*)d_in[23];
    const float* tw3   = (const float*)d_in[24];
    const float* tb3   = (const float*)d_in[25];
    const float* ln2_g = (const float*)d_in[26];
    const float* ln2_b = (const float*)d_in[27];
    const float* wbb   = (const float*)d_in[28];
    const float* bbb   = (const float*)d_in[29];
    float* out = (float*)d_out;

    float* base = nullptr;
    cudaGetSymbolAddress((void**)&base, g_scratch);
    float* q    = base + OFF_Q;
    float* kvb  = base + OFF_KV;
    float* qpr  = base + OFF_QPR;
    float* kvpr = base + OFF_KVPR;
    float* kvp  = base + OFF_KVP;
    float* qt   = base + OFF_QT;
    float* kt   = base + OFF_KT;
    float* A    = base + OFF_A;
    float* opb  = base + OFF_OP;
    float* cat  = base + OFF_CAT;
    float* sa   = base + OFF_SA;
    float* s1   = base + OFF_S1;
    float* h1   = base + OFF_H1;
    float* h2   = base + OFF_H2;
    float* sb   = base + OFF_SB;
    float* updb = base + OFF_UPD;

    const int BIAS_SMEM  = (1536 + 8 * 2 * 64 * 20) * 4;          // 88064
    const int ATTN_SMEM  = (32 * 1024 + 2048 + 32 + 8) * 4;       // 139424
    const int OPAIR_SMEM = (4 * 2 * 32 * 68 + 4 * 2 * 12 * 32 * 2) * 4; // 94208
    cudaFuncSetAttribute(bias_kernel,  cudaFuncAttributeMaxDynamicSharedMemorySize, BIAS_SMEM);
    cudaFuncSetAttribute(attn_kernel,  cudaFuncAttributeMaxDynamicSharedMemorySize, ATTN_SMEM);
    cudaFuncSetAttribute(opair_kernel, cudaFuncAttributeMaxDynamicSharedMemorySize, OPAIR_SMEM);

    // projections (one launch) + merged rotation/packing (kt transposed)
    proj_kernel<<<dim3(24, 16), 256>>>(s_in, wq, bq, wkv, bkv, wqp, bqp, wkvp, bkvp,
                                       q, kvb, qpr, kvpr);
    rotpack_kernel<<<1024, 384>>>(qpr, kvpr, rots, trans, q, kvb, head_w, qt, kt, kvp);

    // p-pass 1 (bias into A) then fused qk/point + softmax (in-place on A)
    bias_kernel<<<2048, 256, BIAS_SMEM>>>(p, wb, bbias, mask, A);
    attn_kernel<<<dim3(32, 12), 256, ATTN_SMEM>>>(qt, kt, A);

    // attention outputs
    av_kernel<<<dim3(32, 12), 128>>>(A, kvb, kvp, cat, opb);
    opair_kernel<<<512, 128, OPAIR_SMEM>>>(p, A, cat);
    op_transform_kernel<<<1024, 96>>>(opb, rots, trans, cat);

    // output projection (split-K=2) + residual + LN1
    cudaMemsetAsync(sa, 0, SZ_S * sizeof(float));
    gemm_splitk_kernel<<<dim3(6, 32, 2), 128>>>(cat, wo, bo, s_in, sa, 1024, 384, 2112, 0);
    ln_kernel<<<1024, 384>>>(sa, ln1_g, ln1_b, s1);

    // transition MLP — split-K=2, relu applied at the consumer's A-load
    cudaMemsetAsync(h1, 0, SZ_S * sizeof(float));
    gemm_splitk_kernel<<<dim3(6, 32, 2), 128>>>(s1, tw1, tb1, nullptr, h1, 1024, 384, 384, 0);
    cudaMemsetAsync(h2, 0, SZ_S * sizeof(float));
    gemm_splitk_kernel<<<dim3(6, 32, 2), 128>>>(h1, tw2, tb2, nullptr, h2, 1024, 384, 384, 1);
    cudaMemsetAsync(sb, 0, SZ_S * sizeof(float));
    gemm_splitk_kernel<<<dim3(6, 32, 2), 128>>>(h2, tw3, tb3, s1,      sb, 1024, 384, 384, 1);
    ln_kernel<<<1024, 384>>>(sb, ln2_g, ln2_b, out);

    // frame update
    gemm_kernel<<<dim3(1, 32), 128>>>(out, wbb, bbb, nullptr, updb, 1024, 6, 384, 0);
    final_pose_kernel<<<4, 256>>>(updb, rots, trans, out);
}

// round 17
// speedup vs baseline: 1.1372x; 1.1372x over previous
#include <cuda_runtime.h>
#include <math.h>
#include <stdint.h>

#define NRES 1024
#define CS   384
#define CATD 2112

typedef unsigned long long ull;

__device__ __forceinline__ void ffma2(ull &d, ull a, ull b) {
    asm("fma.rn.f32x2 %0, %1, %2, %0;" : "+l"(d) : "l"(a), "l"(b));
}
__device__ __forceinline__ float2 unpack2(ull v) {
    float2 r; asm("mov.b64 {%0, %1}, %2;" : "=f"(r.x), "=f"(r.y) : "l"(v)); return r;
}
__device__ __forceinline__ void cp16(uint32_t dst, const void* src) {
    asm volatile("cp.async.cg.shared.global [%0], [%1], 16;" :: "r"(dst), "l"(src));
}
__device__ __forceinline__ void cp_commit() { asm volatile("cp.async.commit_group;"); }
__device__ __forceinline__ void cp_wait1() { asm volatile("cp.async.wait_group 1;"); }
__device__ __forceinline__ void cp_wait0() { asm volatile("cp.async.wait_group 0;"); }

// ---------------- scratch ----------------
static const size_t SZ_Q    = (size_t)NRES*192;
static const size_t SZ_KV   = (size_t)NRES*384;
static const size_t SZ_QPR  = (size_t)NRES*144;
static const size_t SZ_KVPR = (size_t)NRES*432;
static const size_t SZ_KVP  = (size_t)NRES*432;
static const size_t SZ_QT   = (size_t)NRES*384;
static const size_t SZ_KT   = (size_t)NRES*384;
static const size_t SZ_A    = (size_t)12*NRES*NRES;
static const size_t SZ_OP   = (size_t)NRES*288;
static const size_t SZ_CAT  = (size_t)NRES*CATD;
static const size_t SZ_S    = (size_t)NRES*CS;
static const size_t SZ_UPD  = (size_t)NRES*8;

static const size_t OFF_Q    = 0;
static const size_t OFF_KV   = OFF_Q    + SZ_Q;
static const size_t OFF_QPR  = OFF_KV   + SZ_KV;
static const size_t OFF_KVPR = OFF_QPR  + SZ_QPR;
static const size_t OFF_KVP  = OFF_KVPR + SZ_KVPR;
static const size_t OFF_QT   = OFF_KVP  + SZ_KVP;
static const size_t OFF_KT   = OFF_QT   + SZ_QT;
static const size_t OFF_A    = OFF_KT   + SZ_KT;
static const size_t OFF_OP   = OFF_A    + SZ_A;
static const size_t OFF_CAT  = OFF_OP   + SZ_OP;
static const size_t OFF_SA   = OFF_CAT  + SZ_CAT;
static const size_t OFF_S1   = OFF_SA   + SZ_S;
static const size_t OFF_H1   = OFF_S1   + SZ_S;
static const size_t OFF_H2   = OFF_H1   + SZ_S;
static const size_t OFF_SB   = OFF_H2   + SZ_S;
static const size_t OFF_UPD  = OFF_SB   + SZ_S;

__device__ __align__(16) float g_scratch[OFF_UPD + SZ_UPD];

// ---------------- generic GEMM (32x64 tiles, 128 thr): C = A@W^T + bias (+res) ----------------
__global__ void gemm_kernel(const float* __restrict__ A, const float* __restrict__ W,
                            const float* __restrict__ bias, const float* __restrict__ res,
                            float* __restrict__ C, int M, int N, int K, int relu)
{
    __shared__ float As[16][36];
    __shared__ float Ws[16][68];
    const int t = threadIdx.x;          // 128
    const int bm = blockIdx.y * 32, bn = blockIdx.x * 64;
    const int tx = t & 15, ty = t >> 4; // ty 0..7

    float acc[4][4];
#pragma unroll
    for (int r = 0; r < 4; r++)
#pragma unroll
        for (int c = 0; c < 4; c++) acc[r][c] = 0.f;

    const int rowA = t >> 2, kqA = t & 3;
    for (int k0 = 0; k0 < K; k0 += 16) {
        float4 a4 = *(const float4*)(A + (size_t)(bm + rowA) * K + k0 + kqA * 4);
        As[kqA*4+0][rowA] = a4.x; As[kqA*4+1][rowA] = a4.y;
        As[kqA*4+2][rowA] = a4.z; As[kqA*4+3][rowA] = a4.w;
#pragma unroll
        for (int u0 = 0; u0 < 2; u0++) {
            int u = t + u0 * 128;
            int row = u >> 2, kq = u & 3;
            int gn = bn + row;
            float4 w4 = make_float4(0.f, 0.f, 0.f, 0.f);
            if (gn < N) w4 = *(const float4*)(W + (size_t)gn * K + k0 + kq * 4);
            Ws[kq*4+0][row] = w4.x; Ws[kq*4+1][row] = w4.y;
            Ws[kq*4+2][row] = w4.z; Ws[kq*4+3][row] = w4.w;
        }
        __syncthreads();
#pragma unroll
        for (int kk = 0; kk < 16; kk++) {
            float4 av = *(const float4*)&As[kk][ty * 4];
            float4 bv = *(const float4*)&Ws[kk][tx * 4];
            float ar[4] = {av.x, av.y, av.z, av.w};
            float br[4] = {bv.x, bv.y, bv.z, bv.w};
#pragma unroll
            for (int r = 0; r < 4; r++)
#pragma unroll
                for (int c = 0; c < 4; c++) acc[r][c] += ar[r] * br[c];
        }
        __syncthreads();
    }
#pragma unroll
    for (int r = 0; r < 4; r++) {
        int gm = bm + ty * 4 + r;
#pragma unroll
        for (int c = 0; c < 4; c++) {
            int gn = bn + tx * 4 + c;
            if (gn < N) {
                float v = acc[r][c] + bias[gn];
                if (res) v += res[(size_t)gm * N + gn];
                if (relu) v = fmaxf(v, 0.f);
                C[(size_t)gm * N + gn] = v;
            }
        }
    }
}

// ---------------- split-K GEMM (z halves K, atomicAdd into zeroed C) ----------------
__global__ void gemm_splitk_kernel(const float* __restrict__ A, const float* __restrict__ W,
                                   const float* __restrict__ bias, const float* __restrict__ res,
                                   float* __restrict__ C, int M, int N, int K, int relu_in)
{
    __shared__ float As[16][36];
    __shared__ float Ws[16][68];
    const int t = threadIdx.x;          // 128
    const int bm = blockIdx.y * 32, bn = blockIdx.x * 64;
    const int tx = t & 15, ty = t >> 4;
    const int kz = blockIdx.z;          // 0 or 1
    const int kbeg = kz * (K / 2), kend = kbeg + K / 2;

    float acc[4][4];
#pragma unroll
    for (int r = 0; r < 4; r++)
#pragma unroll
        for (int c = 0; c < 4; c++) acc[r][c] = 0.f;

    const int rowA = t >> 2, kqA = t & 3;
    for (int k0 = kbeg; k0 < kend; k0 += 16) {
        float4 a4 = *(const float4*)(A + (size_t)(bm + rowA) * K + k0 + kqA * 4);
        if (relu_in) {
            a4.x = fmaxf(a4.x, 0.f); a4.y = fmaxf(a4.y, 0.f);
            a4.z = fmaxf(a4.z, 0.f); a4.w = fmaxf(a4.w, 0.f);
        }
        As[kqA*4+0][rowA] = a4.x; As[kqA*4+1][rowA] = a4.y;
        As[kqA*4+2][rowA] = a4.z; As[kqA*4+3][rowA] = a4.w;
#pragma unroll
        for (int u0 = 0; u0 < 2; u0++) {
            int u = t + u0 * 128;
            int row = u >> 2, kq = u & 3;
            int gn = bn + row;
            float4 w4 = make_float4(0.f, 0.f, 0.f, 0.f);
            if (gn < N) w4 = *(const float4*)(W + (size_t)gn * K + k0 + kq * 4);
            Ws[kq*4+0][row] = w4.x; Ws[kq*4+1][row] = w4.y;
            Ws[kq*4+2][row] = w4.z; Ws[kq*4+3][row] = w4.w;
        }
        __syncthreads();
#pragma unroll
        for (int kk = 0; kk < 16; kk++) {
            float4 av = *(const float4*)&As[kk][ty * 4];
            float4 bv = *(const float4*)&Ws[kk][tx * 4];
            float ar[4] = {av.x, av.y, av.z, av.w};
            float br[4] = {bv.x, bv.y, bv.z, bv.w};
#pragma unroll
            for (int r = 0; r < 4; r++)
#pragma unroll
                for (int c = 0; c < 4; c++) acc[r][c] += ar[r] * br[c];
        }
        __syncthreads();
    }
#pragma unroll
    for (int r = 0; r < 4; r++) {
        int gm = bm + ty * 4 + r;
#pragma unroll
        for (int c = 0; c < 4; c++) {
            int gn = bn + tx * 4 + c;
            if (gn < N) {
                float v = acc[r][c];
                if (kz == 0) {
                    v += bias[gn];
                    if (res) v += res[(size_t)gm * N + gn];
                }
                atomicAdd(&C[(size_t)gm * N + gn], v);
            }
        }
    }
}

// ---------------- combined projection GEMM (4 weight matrices, 48-col tiles) ----------------
__global__ void proj_kernel(const float* __restrict__ S,
                            const float* __restrict__ wq,   const float* __restrict__ bq,
                            const float* __restrict__ wkv,  const float* __restrict__ bkv,
                            const float* __restrict__ wqp,  const float* __restrict__ bqp,
                            const float* __restrict__ wkvp, const float* __restrict__ bkvp,
                            float* __restrict__ q, float* __restrict__ kvb,
                            float* __restrict__ qpr, float* __restrict__ kvpr)
{
    __shared__ float As[16][68];
    __shared__ float Ws[16][52];
    const int bx = blockIdx.x, bm = blockIdx.y * 64;
    const float *W, *B; float* O; int nbase, N;
    if (bx < 4)       { W = wq;   B = bq;   O = q;    nbase = bx * 48;        N = 192; }
    else if (bx < 12) { W = wkv;  B = bkv;  O = kvb;  nbase = (bx - 4) * 48;  N = 384; }
    else if (bx < 15) { W = wqp;  B = bqp;  O = qpr;  nbase = (bx - 12) * 48; N = 144; }
    else              { W = wkvp; B = bkvp; O = kvpr; nbase = (bx - 15) * 48; N = 432; }

    const int t = threadIdx.x;           // 256
    const int tx = t & 15, ty = t >> 4;
    const int row = t >> 2, kq = t & 3;

    float acc[4][3];
#pragma unroll
    for (int r = 0; r < 4; r++)
#pragma unroll
        for (int c = 0; c < 3; c++) acc[r][c] = 0.f;

    for (int k0 = 0; k0 < 384; k0 += 16) {
        float4 a4 = *(const float4*)(S + (size_t)(bm + row) * 384 + k0 + kq * 4);
        As[kq*4+0][row] = a4.x; As[kq*4+1][row] = a4.y;
        As[kq*4+2][row] = a4.z; As[kq*4+3][row] = a4.w;
        if (t < 192) {
            float4 w4 = *(const float4*)(W + (size_t)(nbase + row) * 384 + k0 + kq * 4);
            Ws[kq*4+0][row] = w4.x; Ws[kq*4+1][row] = w4.y;
            Ws[kq*4+2][row] = w4.z; Ws[kq*4+3][row] = w4.w;
        }
        __syncthreads();
#pragma unroll
        for (int kk = 0; kk < 16; kk++) {
            float4 av = *(const float4*)&As[kk][ty * 4];
            float ar[4] = {av.x, av.y, av.z, av.w};
            float w0 = Ws[kk][tx*3 + 0], w1 = Ws[kk][tx*3 + 1], w2 = Ws[kk][tx*3 + 2];
#pragma unroll
            for (int r = 0; r < 4; r++) {
                acc[r][0] += ar[r] * w0; acc[r][1] += ar[r] * w1; acc[r][2] += ar[r] * w2;
            }
        }
        __syncthreads();
    }
#pragma unroll
    for (int r = 0; r < 4; r++) {
        int gm = bm + ty * 4 + r;
#pragma unroll
        for (int c = 0; c < 3; c++) {
            int n = nbase + tx * 3 + c;
            O[(size_t)gm * N + n] = acc[r][c] + B[n];
        }
    }
}

// ---------------- rotate points + pack q~/k~ (kt transposed to [h][c][j]) ----------------
__global__ void rotpack_kernel(const float* __restrict__ qpr, const float* __restrict__ kvpr,
                               const float* __restrict__ rots, const float* __restrict__ trans,
                               const float* __restrict__ q, const float* __restrict__ kv,
                               const float* __restrict__ head_w,
                               float* __restrict__ qt, float* __restrict__ kt_t,
                               float* __restrict__ kvp_out)
{
    __shared__ float R[9], tr[3];
    __shared__ float qp_s[144], kvp_s[432], q2_s[48], k2_s[48];
    const int i = blockIdx.x, t = threadIdx.x; // 384 threads
    if (t < 9) R[t] = rots[i * 9 + t];
    if (t < 3) tr[t] = trans[i * 3 + t];
    __syncthreads();
    if (t < 48) {
        float r0 = qpr[(size_t)i * 144 + 0 * 48 + t];
        float r1 = qpr[(size_t)i * 144 + 1 * 48 + t];
        float r2 = qpr[(size_t)i * 144 + 2 * 48 + t];
        float v0 = R[0]*r0 + R[1]*r1 + R[2]*r2 + tr[0];
        float v1 = R[3]*r0 + R[4]*r1 + R[5]*r2 + tr[1];
        float v2 = R[6]*r0 + R[7]*r1 + R[8]*r2 + tr[2];
        qp_s[t * 3 + 0] = v0; qp_s[t * 3 + 1] = v1; qp_s[t * 3 + 2] = v2;
        q2_s[t] = v0*v0 + v1*v1 + v2*v2;
    } else if (t < 192) {
        int u = t - 48; // < 144
        float r0 = kvpr[(size_t)i * 432 + 0 * 144 + u];
        float r1 = kvpr[(size_t)i * 432 + 1 * 144 + u];
        float r2 = kvpr[(size_t)i * 432 + 2 * 144 + u];
        float v0 = R[0]*r0 + R[1]*r1 + R[2]*r2 + tr[0];
        float v1 = R[3]*r0 + R[4]*r1 + R[5]*r2 + tr[1];
        float v2 = R[6]*r0 + R[7]*r1 + R[8]*r2 + tr[2];
        kvp_s[u * 3 + 0] = v0; kvp_s[u * 3 + 1] = v1; kvp_s[u * 3 + 2] = v2;
        kvp_out[(size_t)i * 432 + u * 3 + 0] = v0;
        kvp_out[(size_t)i * 432 + u * 3 + 1] = v1;
        kvp_out[(size_t)i * 432 + u * 3 + 2] = v2;
        int idx = u % 12, h = u / 12;
        if (idx < 4) k2_s[h * 4 + idx] = v0*v0 + v1*v1 + v2*v2;
    }
    __syncthreads();

    const int h = t >> 5, c = t & 31;
    const float hw = -0.5f * log1pf(expf(head_w[h])) * 0.13608276f;
    float qv = 0.f, kvv = 0.f;
    if (c < 16) {
        qv  = q [(size_t)i * 192 + h * 16 + c] * 0.14433757f;
        kvv = kv[(size_t)i * 384 + h * 32 + c];
    } else if (c < 28) {
        qv  = qp_s[h * 12 + (c - 16)];
        kvv = -2.f * hw * kvp_s[h * 36 + (c - 16)];
    } else if (c == 28) {
        const float* s = q2_s + h * 4;
        qv  = hw * (s[0] + s[1] + s[2] + s[3]);
        kvv = 1.f;
    } else if (c == 29) {
        const float* s = k2_s + h * 4;
        qv  = 1.f;
        kvv = hw * (s[0] + s[1] + s[2] + s[3]);
    }
    qt[((size_t)i * 12 + h) * 32 + c] = qv;
    kt_t[(((size_t)h * 32 + c) << 10) + i] = kvv;   // [h][c][j] transposed
}

// ---------------- bias over p (p-pass 1): cp.async double-buffered ----------------
__global__ void __launch_bounds__(256, 2)
bias_kernel(const float* __restrict__ p, const float* __restrict__ wb,
            const float* __restrict__ bbias, const float* __restrict__ mask,
            float* __restrict__ A)
{
    extern __shared__ float sh[];
    float* wb_s = sh;                              // [12][128] = 1536
    const int t = threadIdx.x, w = t >> 5, lane = t & 31;
    float* p_w = sh + 1536 + w * (2 * 64 * 20);

    for (int u = t; u < 384; u += 256)
        ((float4*)wb_s)[u] = ((const float4*)wb)[u];
    __syncthreads();

    const size_t pair0 = (size_t)blockIdx.x * 512 + (size_t)w * 64;
    const float* psrc = p + pair0 * 128;
    uint32_t pb0 = (uint32_t)__cvta_generic_to_shared(p_w);
    const uint32_t pbuf[2] = {pb0, pb0 + 64 * 20 * 4};

#pragma unroll
    for (int v = 0; v < 8; v++) {
        int u = lane + v * 32;
        int row = u >> 2, c4 = u & 3;
        cp16(pbuf[0] + (uint32_t)(row * 20 + c4 * 4) * 4,
             psrc + (size_t)row * 128 + c4 * 4);
    }
    cp_commit();

    ull acc[2][12];
#pragma unroll
    for (int pp = 0; pp < 2; pp++)
#pragma unroll
        for (int h = 0; h < 12; h++) acc[pp][h] = 0ull;

#pragma unroll
    for (int ch = 0; ch < 8; ch++) {
        if (ch < 7) {
            const float* src = psrc + (ch + 1) * 16;
            uint32_t db = pbuf[(ch + 1) & 1];
#pragma unroll
            for (int v = 0; v < 8; v++) {
                int u = lane + v * 32;
                int row = u >> 2, c4 = u & 3;
                cp16(db + (uint32_t)(row * 20 + c4 * 4) * 4,
                     src + (size_t)row * 128 + c4 * 4);
            }
            cp_commit();
            cp_wait1();
        } else {
            cp_wait0();
        }
        __syncwarp();
        const float* pw = p_w + (ch & 1) * (64 * 20);
        const ulonglong2* prow0 = (const ulonglong2*)(pw + (size_t)lane * 20);
        const ulonglong2* prow1 = (const ulonglong2*)(pw + (size_t)(lane + 32) * 20);
        const float* wbq = wb_s + ch * 16;
#pragma unroll
        for (int z4 = 0; z4 < 4; z4++) {
            ulonglong2 a0 = prow0[z4], a1 = prow1[z4];
#pragma unroll
            for (int h = 0; h < 12; h++) {
                ulonglong2 wv = *(const ulonglong2*)(wbq + h * 128 + z4 * 4);
                ffma2(acc[0][h], wv.x, a0.x); ffma2(acc[0][h], wv.y, a0.y);
                ffma2(acc[1][h], wv.x, a1.x); ffma2(acc[1][h], wv.y, a1.y);
            }
        }
        __syncwarp();
    }

#pragma unroll
    for (int pp = 0; pp < 2; pp++) {
        const size_t pair = pair0 + lane + pp * 32;
        const int i = (int)(pair >> 10), j = (int)(pair & 1023);
        const float mterm = 100000.0f * (mask[i] * mask[j] - 1.0f);
#pragma unroll
        for (int h = 0; h < 12; h++) {
            float2 r = unpack2(acc[pp][h]);
            A[((size_t)h << 20) + pair] = 0.57735027f * (r.x + r.y + bbias[h]) + mterm;
        }
    }
}

// ---------------- fused qk/point logits + row softmax (kt from global, R15 shape) ----------------
__global__ void __launch_bounds__(256, 4)
attn_kernel(const float* __restrict__ qt, const float* __restrict__ kt_t,
            float* __restrict__ A)
{
    __shared__ float qd_s[32 * 64];   // q duplicated: [i_local][c*2 | c*2+1]
    __shared__ float red[32];
    __shared__ float rowstat[8];
    const int t = threadIdx.x;
    const int lane = t & 31, w = t >> 5;
    const int h = blockIdx.y;
    const int i0 = blockIdx.x * 32;
    float* Ah = A + ((size_t)h << 20);
    const float* kth = kt_t + ((size_t)h << 15);   // [32][1024]

    for (int u = t; u < 1024; u += 256) {
        int il = u >> 5, c = u & 31;
        float v = qt[((size_t)(i0 + il) * 12 + h) * 32 + c];
        qd_s[il * 64 + c * 2]     = v;
        qd_s[il * 64 + c * 2 + 1] = v;
    }
    __syncthreads();

    for (int g = 0; g < 8; g++) {
        const int ibase = i0 + g * 4;

        float4 lg4[4];
#pragma unroll
        for (int r = 0; r < 4; r++)
            lg4[r] = *(const float4*)&Ah[(size_t)(ibase + r) * 1024 + 4 * t];

        ull acc[4][2];
#pragma unroll
        for (int r = 0; r < 4; r++) { acc[r][0] = 0ull; acc[r][1] = 0ull; }

#pragma unroll 4
        for (int c2 = 0; c2 < 16; c2++) {
            float4 k0 = *(const float4*)&kth[(size_t)(2 * c2) * 1024 + 4 * t];
            float4 k1 = *(const float4*)&kth[(size_t)(2 * c2 + 1) * 1024 + 4 * t];
            ulonglong2 k0u = *(ulonglong2*)&k0;
            ulonglong2 k1u = *(ulonglong2*)&k1;
#pragma unroll
            for (int r = 0; r < 4; r++) {
                ulonglong2 q2 = *(const ulonglong2*)&qd_s[(g * 4 + r) * 64 + c2 * 4];
                ffma2(acc[r][0], q2.x, k0u.x); ffma2(acc[r][1], q2.x, k0u.y);
                ffma2(acc[r][0], q2.y, k1u.x); ffma2(acc[r][1], q2.y, k1u.y);
            }
        }
#pragma unroll
        for (int r = 0; r < 4; r++) {
            float2 lo = unpack2(acc[r][0]);
            float2 hi = unpack2(acc[r][1]);
            lg4[r].x += lo.x; lg4[r].y += lo.y;
            lg4[r].z += hi.x; lg4[r].w += hi.y;
        }

        float m4[4];
#pragma unroll
        for (int r = 0; r < 4; r++)
            m4[r] = fmaxf(fmaxf(lg4[r].x, lg4[r].y), fmaxf(lg4[r].z, lg4[r].w));
#pragma unroll
        for (int off = 16; off >= 1; off >>= 1)
#pragma unroll
            for (int r = 0; r < 4; r++)
                m4[r] = fmaxf(m4[r], __shfl_xor_sync(0xffffffffu, m4[r], off));
        if (lane == 0)
#pragma unroll
            for (int r = 0; r < 4; r++) red[r * 8 + w] = m4[r];
        __syncthreads();
        if (t < 4) {
            float v = red[t * 8];
#pragma unroll
            for (int ww = 1; ww < 8; ww++) v = fmaxf(v, red[t * 8 + ww]);
            rowstat[t] = v;
        }
        __syncthreads();

        float s4[4];
#pragma unroll
        for (int r = 0; r < 4; r++) {
            const float M = rowstat[r];
            lg4[r].x = __expf(lg4[r].x - M);
            lg4[r].y = __expf(lg4[r].y - M);
            lg4[r].z = __expf(lg4[r].z - M);
            lg4[r].w = __expf(lg4[r].w - M);
            s4[r] = lg4[r].x + lg4[r].y + lg4[r].z + lg4[r].w;
        }
#pragma unroll
        for (int off = 16; off >= 1; off >>= 1)
#pragma unroll
            for (int r = 0; r < 4; r++)
                s4[r] += __shfl_xor_sync(0xffffffffu, s4[r], off);
        if (lane == 0)
#pragma unroll
            for (int r = 0; r < 4; r++) red[r * 8 + w] = s4[r];
        __syncthreads();
        if (t < 4) {
            float v = red[t * 8];
#pragma unroll
            for (int ww = 1; ww < 8; ww++) v += red[t * 8 + ww];
            rowstat[4 + t] = 1.f / v;
        }
        __syncthreads();

#pragma unroll
        for (int r = 0; r < 4; r++) {
            const float inv = rowstat[4 + r];
            float4 o = make_float4(lg4[r].x * inv, lg4[r].y * inv,
                                   lg4[r].z * inv, lg4[r].w * inv);
            *(float4*)&Ah[(size_t)(ibase + r) * 1024 + 4 * t] = o;
        }
        __syncthreads();
    }
}

// ---------------- O = A_h @ [v | vp]  (32-row tiles, split-j=2, atomicAdd) ----------------
__global__ void av_kernel(const float* __restrict__ A, const float* __restrict__ kv,
                          const float* __restrict__ kvp,
                          float* __restrict__ cat, float* __restrict__ opb)
{
    __shared__ float A_s[32][33];
    __shared__ float B_s[32][40];
    const int h = blockIdx.y, i0 = blockIdx.x * 32;
    const int kz = blockIdx.z;           // 0 or 1: j-halves
    const int tid = threadIdx.x;         // 128
    const int m = tid & 31, sct = tid >> 5;
    const float* Ah = A + ((size_t)h << 20);
    float acc[10];
#pragma unroll
    for (int n = 0; n < 10; n++) acc[n] = 0.f;

    const int kbeg = kz * 512, kend = kbeg + 512;
    for (int k0 = kbeg; k0 < kend; k0 += 32) {
        for (int u = tid; u < 1024; u += 128) {
            int mm = u >> 5, kk = u & 31;
            A_s[kk][mm] = Ah[(size_t)(i0 + mm) * 1024 + k0 + kk];
        }
        for (int u = tid; u < 1280; u += 128) {
            int kk = u / 40, n = u % 40;
            int jgl = k0 + kk;
            B_s[kk][n] = (n < 16) ? kv [(size_t)jgl * 384 + h * 32 + 16 + n]
                                  : kvp[(size_t)jgl * 432 + h * 36 + 12 + (n - 16)];
        }
        __syncthreads();
#pragma unroll
        for (int kk = 0; kk < 32; kk++) {
            float a = A_s[kk][m];
#pragma unroll
            for (int n2 = 0; n2 < 5; n2++) {
                float2 b = *(const float2*)&B_s[kk][sct * 10 + n2 * 2];
                acc[n2*2+0] += a * b.x; acc[n2*2+1] += a * b.y;
            }
        }
        __syncthreads();
    }
    const int i = i0 + m;
#pragma unroll
    for (int n = 0; n < 10; n++) {
        int gn = sct * 10 + n;
        if (gn < 16) atomicAdd(&cat[(size_t)i * CATD + h * 16 + gn], acc[n]);
        else         atomicAdd(&opb[(size_t)i * 288 + h * 24 + (gn - 16)], acc[n]);
    }
}

// ---------------- opair (p-pass 2): cp.async double-buffered ----------------
__global__ void __launch_bounds__(128, 2)
opair_kernel(const float* __restrict__ p, const float* __restrict__ A,
             float* __restrict__ cat)
{
    extern __shared__ float sh[];
    const int t = threadIdx.x;
    const int w = t >> 5, lane = t & 31;
    const int iw = w >> 1, zh = w & 1;
    const int i = blockIdx.x * 2 + iw;
    float* p_w = sh + w * (2 * 32 * 68);
    ull*   a_w = (ull*)(sh + 4 * 2 * 32 * 68) + w * (2 * 12 * 32);

    const float* psrc = p + (size_t)i * 1024 * 128 + zh * 64;
    uint32_t pb0 = (uint32_t)__cvta_generic_to_shared(p_w);
    const uint32_t pbuf[2] = {pb0, pb0 + 32 * 68 * 4};

#pragma unroll
    for (int v = 0; v < 16; v++) {
        int u = lane + v * 32;
        int row = u >> 4, c4 = u & 15;
        cp16(pbuf[0] + (uint32_t)(row * 68 + c4 * 4) * 4,
             psrc + (size_t)row * 128 + c4 * 4);
    }
    cp_commit();
#pragma unroll
    for (int v = 0; v < 12; v++) {
        int u = lane + v * 32;
        int h = u >> 5, jj = u & 31;
        float a = A[((size_t)h << 20) + (size_t)i * 1024 + jj];
        float2 a2 = make_float2(a, a);
        a_w[h * 32 + jj] = *(ull*)&a2;
    }

    ull acc[12];
#pragma unroll
    for (int h = 0; h < 12; h++) acc[h] = 0ull;

    for (int c = 0; c < 32; c++) {
        if (c < 31) {
            const int j1 = (c + 1) * 32;
            uint32_t db = pbuf[(c + 1) & 1];
            const float* src = psrc + (size_t)j1 * 128;
#pragma unroll
            for (int v = 0; v < 16; v++) {
                int u = lane + v * 32;
                int row = u >> 4, c4 = u & 15;
                cp16(db + (uint32_t)(row * 68 + c4 * 4) * 4,
                     src + (size_t)row * 128 + c4 * 4);
            }
            cp_commit();
            ull* ab = a_w + ((c + 1) & 1) * (12 * 32);
#pragma unroll
            for (int v = 0; v < 12; v++) {
                int u = lane + v * 32;
                int h = u >> 5, jj = u & 31;
                float a = A[((size_t)h << 20) + (size_t)i * 1024 + j1 + jj];
                float2 a2 = make_float2(a, a);
                ab[h * 32 + jj] = *(ull*)&a2;
            }
            cp_wait1();
        } else {
            cp_wait0();
        }
        __syncwarp();
        const float* pw = p_w + (c & 1) * (32 * 68);
        const ull* aw = a_w + (c & 1) * (12 * 32);
#pragma unroll 8
        for (int jj = 0; jj < 32; jj++) {
            ull pv = *(const ull*)&pw[jj * 68 + lane * 2];
            const ull* arow = aw + jj;
#pragma unroll
            for (int h = 0; h < 12; h++)
                ffma2(acc[h], arow[h * 32], pv);
        }
        __syncwarp();
    }
#pragma unroll
    for (int h = 0; h < 12; h++) {
        float2 r = unpack2(acc[h]);
        *(float2*)&cat[(size_t)i * CATD + 576 + h * 128 + zh * 64 + lane * 2] = r;
    }
}

// ---------------- transform op back to local frame + norms ----------------
__global__ void op_transform_kernel(const float* __restrict__ opb, const float* __restrict__ rots,
                                    const float* __restrict__ trans, float* __restrict__ cat)
{
    const int i = blockIdx.x, t = threadIdx.x; // 96 points
    __shared__ float R[9], tr[3];
    if (t < 9) R[t] = rots[i * 9 + t];
    if (t < 3) tr[t] = trans[i * 3 + t];
    __syncthreads();
    float v0 = opb[(size_t)i * 288 + t * 3 + 0] - tr[0];
    float v1 = opb[(size_t)i * 288 + t * 3 + 1] - tr[1];
    float v2 = opb[(size_t)i * 288 + t * 3 + 2] - tr[2];
    float l0 = R[0]*v0 + R[3]*v1 + R[6]*v2;
    float l1 = R[1]*v0 + R[4]*v1 + R[7]*v2;
    float l2 = R[2]*v0 + R[5]*v1 + R[8]*v2;
    float* c = cat + (size_t)i * CATD;
    c[192 + t] = l0;
    c[288 + t] = l1;
    c[384 + t] = l2;
    c[480 + t] = sqrtf(l0*l0 + l1*l1 + l2*l2 + 1e-8f);
}

// ---------------- LayerNorm (row = 384) ----------------
__global__ void ln_kernel(const float* __restrict__ x, const float* __restrict__ g,
                          const float* __restrict__ b, float* __restrict__ out)
{
    __shared__ float s1[384], s2[384];
    const int row = blockIdx.x, t = threadIdx.x;
    float v = x[(size_t)row * 384 + t];
    s1[t] = v; s2[t] = v * v;
    __syncthreads();
    if (t < 128) { s1[t] += s1[t + 256]; s2[t] += s2[t + 256]; }
    __syncthreads();
    for (int s = 128; s > 0; s >>= 1) {
        if (t < s) { s1[t] += s1[t + s]; s2[t] += s2[t + s]; }
        __syncthreads();
    }
    float mean = s1[0] * (1.f / 384.f);
    float var  = s2[0] * (1.f / 384.f) - mean * mean;
    float inv  = rsqrtf(var + 1e-5f);
    out[(size_t)row * 384 + t] = (v - mean) * inv * g[t] + b[t];
}

// ---------------- final quaternion / frame update ----------------
__global__ void final_pose_kernel(const float* __restrict__ upd, const float* __restrict__ rots,
                                  const float* __restrict__ trans, float* __restrict__ out)
{
    const int i = blockIdx.x * blockDim.x + threadIdx.x;
    if (i >= NRES) return;
    const float* u = upd + (size_t)i * 6;
    float x = u[0], y = u[1], z = u[2];
    float inv = rsqrtf(1.f + x*x + y*y + z*z);
    float w = inv; x *= inv; y *= inv; z *= inv;
    float U[9];
    U[0] = w*w + x*x - y*y - z*z; U[1] = 2.f*(x*y - w*z);       U[2] = 2.f*(x*z + w*y);
    U[3] = 2.f*(x*y + w*z);       U[4] = w*w - x*x + y*y - z*z; U[5] = 2.f*(y*z - w*x);
    U[6] = 2.f*(x*z - w*y);       U[7] = 2.f*(y*z + w*x);       U[8] = w*w - x*x - y*y + z*z;
    const float* R = rots + (size_t)i * 9;
    float* Ro = out + 393216 + (size_t)i * 9;
#pragma unroll
    for (int r = 0; r < 3; r++)
#pragma unroll
        for (int c = 0; c < 3; c++)
            Ro[r*3+c] = R[r*3+0]*U[0*3+c] + R[r*3+1]*U[1*3+c] + R[r*3+2]*U[2*3+c];
    float* To = out + 402432 + (size_t)i * 3;
#pragma unroll
    for (int r = 0; r < 3; r++)
        To[r] = R[r*3+0]*u[3] + R[r*3+1]*u[4] + R[r*3+2]*u[5] + trans[(size_t)i*3 + r];
}

// ---------------- launch ----------------
extern "C" void kernel_launch(void* const* d_in, const int* in_sizes, int n_in,
                              void* d_out, int out_size)
{
    const float* s_in  = (const float*)d_in[0];
    const float* p     = (const float*)d_in[1];
    const float* rots  = (const float*)d_in[2];
    const float* trans = (const float*)d_in[3];
    const float* mask  = (const float*)d_in[4];
    const float* wq    = (const float*)d_in[5];
    const float* bq    = (const float*)d_in[6];
    const float* wkv   = (const float*)d_in[7];
    const float* bkv   = (const float*)d_in[8];
    const float* wqp   = (const float*)d_in[9];
    const float* bqp   = (const float*)d_in[10];
    const float* wkvp  = (const float*)d_in[11];
    const float* bkvp  = (const float*)d_in[12];
    const float* wb    = (const float*)d_in[13];
    const float* bbias = (const float*)d_in[14];
    const float* head_w= (const float*)d_in[15];
    const float* wo    = (const float*)d_in[16];
    const float* bo    = (const float*)d_in[17];
    const float* ln1_g = (const float*)d_in[18];
    const float* ln1_b = (const float*)d_in[19];
    const float* tw1   = (const float*)d_in[20];
    const float* tb1   = (const float*)d_in[21];
    const float* tw2   = (const float*)d_in[22];
    const float* tb2   = (const float*)d_in[23];
    const float* tw3   = (const float*)d_in[24];
    const float* tb3   = (const float*)d_in[25];
    const float* ln2_g = (const float*)d_in[26];
    const float* ln2_b = (const float*)d_in[27];
    const float* wbb   = (const float*)d_in[28];
    const float* bbb   = (const float*)d_in[29];
    float* out = (float*)d_out;

    float* base = nullptr;
    cudaGetSymbolAddress((void**)&base, g_scratch);
    float* q    = base + OFF_Q;
    float* kvb  = base + OFF_KV;
    float* qpr  = base + OFF_QPR;
    float* kvpr = base + OFF_KVPR;
    float* kvp  = base + OFF_KVP;
    float* qt   = base + OFF_QT;
    float* kt   = base + OFF_KT;
    float* A    = base + OFF_A;
    float* opb  = base + OFF_OP;
    float* cat  = base + OFF_CAT;
    float* sa   = base + OFF_SA;
    float* s1   = base + OFF_S1;
    float* h1   = base + OFF_H1;
    float* h2   = base + OFF_H2;
    float* sb   = base + OFF_SB;
    float* updb = base + OFF_UPD;

    const int BIAS_SMEM  = (1536 + 8 * 2 * 64 * 20) * 4;          // 88064
    const int OPAIR_SMEM = (4 * 2 * 32 * 68 + 4 * 2 * 12 * 32 * 2) * 4; // 94208
    cudaFuncSetAttribute(bias_kernel,  cudaFuncAttributeMaxDynamicSharedMemorySize, BIAS_SMEM);
    cudaFuncSetAttribute(opair_kernel, cudaFuncAttributeMaxDynamicSharedMemorySize, OPAIR_SMEM);

    // projections (one launch) + merged rotation/packing (kt transposed)
    proj_kernel<<<dim3(24, 16), 256>>>(s_in, wq, bq, wkv, bkv, wqp, bqp, wkvp, bkvp,
                                       q, kvb, qpr, kvpr);
    rotpack_kernel<<<1024, 384>>>(qpr, kvpr, rots, trans, q, kvb, head_w, qt, kt, kvp);

    // p-pass 1 (bias into A) then fused qk/point + softmax (in-place on A)
    bias_kernel<<<2048, 256, BIAS_SMEM>>>(p, wb, bbias, mask, A);
    attn_kernel<<<dim3(32, 12), 256>>>(qt, kt, A);

    // attention outputs (av split-j=2 via atomicAdd into zeroed cat/opb)
    cudaMemsetAsync(cat, 0, SZ_CAT * sizeof(float));
    cudaMemsetAsync(opb, 0, SZ_OP * sizeof(float));
    av_kernel<<<dim3(32, 12, 2), 128>>>(A, kvb, kvp, cat, opb);
    opair_kernel<<<512, 128, OPAIR_SMEM>>>(p, A, cat);
    op_transform_kernel<<<1024, 96>>>(opb, rots, trans, cat);

    // output projection (split-K=2) + residual + LN1
    cudaMemsetAsync(sa, 0, SZ_S * sizeof(float));
    gemm_splitk_kernel<<<dim3(6, 32, 2), 128>>>(cat, wo, bo, s_in, sa, 1024, 384, 2112, 0);
    ln_kernel<<<1024, 384>>>(sa, ln1_g, ln1_b, s1);

    // transition MLP — split-K=2, relu applied at the consumer's A-load
    cudaMemsetAsync(h1, 0, SZ_S * sizeof(float));
    gemm_splitk_kernel<<<dim3(6, 32, 2), 128>>>(s1, tw1, tb1, nullptr, h1, 1024, 384, 384, 0);
    cudaMemsetAsync(h2, 0, SZ_S * sizeof(float));
    gemm_splitk_kernel<<<dim3(6, 32, 2), 128>>>(h1, tw2, tb2, nullptr, h2, 1024, 384, 384, 1);
    cudaMemsetAsync(sb, 0, SZ_S * sizeof(float));
    gemm_splitk_kernel<<<dim3(6, 32, 2), 128>>>(h2, tw3, tb3, s1,      sb, 1024, 384, 384, 1);
    ln_kernel<<<1024, 384>>>(sb, ln2_g, ln2_b, out);

    // frame update
    gemm_kernel<<<dim3(1, 32), 128>>>(out, wbb, bbb, nullptr, updb, 1024, 6, 384, 0);
    final_pose_kernel<<<4, 256>>>(updb, rots, trans, out);
}